// round 3
// baseline (speedup 1.0000x reference)
#include <cuda_runtime.h>

// Problem constants (fixed per metadata)
#define EMAX 160000
#define NMAX 10000

// Scratch (device globals — allocation-free)
__device__ float g_ex[EMAX * 4];      // exp(score) per edge/head
__device__ float g_v[EMAX * 24];      // v per edge (m2*d2 = 24)
__device__ float g_denom[NMAX * 4];   // softmax denominator per node/head

// Shared memory layout (in floats)
#define OFF_W2T 0        // [64][768]  W2 transposed (k-major)
#define OFF_W1T 49152    // [32][64]   W1 transposed (i-major)
#define OFF_HT  51200    // [64][32]   H (relu MLP out), k-major
#define OFF_BAS 53248    // [32][18]   basis per edge
#define OFF_FG  53824    // [32][48]   gathered f[src]
#define OFF_UNI 55360    // union: EF [32][33] (1056) / conv [32][72] (2304)
#define OFF_SRC 57664    // [32] int
#define OFF_DST 57696    // [32] int
#define SMEM_FLOATS 57728
#define SMEM_BYTES (SMEM_FLOATS * 4)   // 230912 B < 232448 B limit

__global__ __launch_bounds__(256, 1)
void passA(const int* __restrict__ src, const int* __restrict__ dst,
           const float* __restrict__ basis, const float* __restrict__ efeat,
           const float* __restrict__ f, const float* __restrict__ W1,
           const float* __restrict__ b1, const float* __restrict__ W2,
           const float* __restrict__ b2, int E)
{
    extern __shared__ float sm[];
    float* W2t = sm + OFF_W2T;
    float* W1t = sm + OFF_W1T;
    float* Ht  = sm + OFF_HT;
    float* bas = sm + OFF_BAS;
    float* fg  = sm + OFF_FG;
    float* uni = sm + OFF_UNI;
    int* srcs  = (int*)(sm + OFF_SRC);
    int* dsts  = (int*)(sm + OFF_DST);

    const int t = threadIdx.x;

    // ---- one-time per block: stage W2 (transposed, k-major) and W1 (transposed) ----
    for (int idx = t; idx < 768 * 64; idx += 256) {
        int o = idx >> 6, h = idx & 63;       // W2[o][h], o<768, h<64
        W2t[h * 768 + o] = W2[idx];
    }
    for (int idx = t; idx < 64 * 32; idx += 256) {
        int j = idx >> 5, i = idx & 31;       // W1[j][i], j<64, i<32
        W1t[i * 64 + j] = W1[idx];
    }
    __syncthreads();

    // GEMM thread mapping: 4 c-quadrants x (8 e-groups x 8 m-groups)
    const int cq = t >> 6;          // 0..3
    const int ty = (t >> 3) & 7;    // 0..7
    const int tx = t & 7;           // 0..7
    const int e0 = ty * 4;
    const int m0 = tx * 4;

    const int ntiles = (E + 31) >> 5;
    for (int tile = blockIdx.x; tile < ntiles; tile += gridDim.x) {
        const int eg0 = tile << 5;

        // ---- stage 1: edge indices ----
        if (t < 32) {
            int ee = min(eg0 + t, E - 1);
            srcs[t] = src[ee];
            dsts[t] = dst[ee];
        }
        __syncthreads();

        // ---- stage 2: edge feats (into union region), basis, gathered f ----
        for (int idx = t; idx < 1024; idx += 256) {      // EF [32][33] padded
            int e = idx >> 5, i = idx & 31;
            int ee = min(eg0 + e, E - 1);
            uni[e * 33 + i] = efeat[ee * 32 + i];
        }
        for (int idx = t; idx < 576; idx += 256) {       // basis [32][18]
            int e = idx / 18, k = idx - e * 18;
            int ee = min(eg0 + e, E - 1);
            bas[e * 18 + k] = basis[ee * 18 + k];
        }
        for (int idx = t; idx < 1536; idx += 256) {      // f gather [32][48]
            int e = idx / 48, r = idx - e * 48;
            fg[idx] = f[srcs[e] * 48 + r];
        }
        __syncthreads();

        // ---- stage 3a: tmp[e][m][d] into registers (48/thread) ----
        // m = m1*2 + rep ; tmp = sum_d1 f[src][m1][d1] * basis[d1][rep*3+d]
        float tmpreg[4][4][3];
        #pragma unroll
        for (int ie = 0; ie < 4; ie++) {
            int e = e0 + ie;
            #pragma unroll
            for (int im = 0; im < 4; im++) {
                int m = m0 + im;
                int m1 = m >> 1, rep = m & 1;
                #pragma unroll
                for (int d = 0; d < 3; d++) {
                    float s = 0.f;
                    #pragma unroll
                    for (int d1 = 0; d1 < 3; d1++)
                        s += fg[e * 48 + m1 * 3 + d1] * bas[e * 18 + d1 * 6 + rep * 3 + d];
                    tmpreg[ie][im][d] = s;
                }
            }
        }

        // ---- stage 3b: H = relu(EF @ W1^T + b1), stored k-major Ht[j][e] ----
        {
            int e = t & 31, jg = t >> 5;
            #pragma unroll
            for (int jj = 0; jj < 8; jj++) {
                int j = jg * 8 + jj;
                float acc = __ldg(&b1[j]);
                #pragma unroll
                for (int i = 0; i < 32; i++)
                    acc += uni[e * 33 + i] * W1t[i * 64 + j];   // EF lane-strided, W1t broadcast
                Ht[j * 32 + e] = fmaxf(acc, 0.f);
            }
        }
        __syncthreads();   // Ht ready; EF (union) now dead -> conv may overwrite

        // ---- stage 4: RW GEMM fused with conv contraction ----
        float* conv = uni;   // [32][72]: c*3+d flattened, k|q|v = c 0..7|8..15|16..23
        #pragma unroll 1
        for (int cg = 0; cg < 6; cg++) {
            const int c = cg * 4 + cq;
            float acc[4][4];
            {
                float bvals[4];
                #pragma unroll
                for (int im = 0; im < 4; im++)
                    bvals[im] = __ldg(&b2[c * 32 + m0 + im]);
                #pragma unroll
                for (int ie = 0; ie < 4; ie++)
                    #pragma unroll
                    for (int im = 0; im < 4; im++)
                        acc[ie][im] = bvals[im];
            }
            const float* Wp = W2t + c * 32 + m0;
            #pragma unroll 16
            for (int k = 0; k < 64; k++) {
                float4 av = *reinterpret_cast<const float4*>(Ht + k * 32 + e0);
                float4 bv = *reinterpret_cast<const float4*>(Wp + k * 768);
                acc[0][0] += av.x * bv.x; acc[0][1] += av.x * bv.y; acc[0][2] += av.x * bv.z; acc[0][3] += av.x * bv.w;
                acc[1][0] += av.y * bv.x; acc[1][1] += av.y * bv.y; acc[1][2] += av.y * bv.z; acc[1][3] += av.y * bv.w;
                acc[2][0] += av.z * bv.x; acc[2][1] += av.z * bv.y; acc[2][2] += av.z * bv.z; acc[2][3] += av.z * bv.w;
                acc[3][0] += av.w * bv.x; acc[3][1] += av.w * bv.y; acc[3][2] += av.w * bv.z; acc[3][3] += av.w * bv.w;
            }
            // local conv partial: pc[e][d] = sum_m rw[e][c][m] * tmp[e][m][d]
            float pc[4][3];
            #pragma unroll
            for (int ie = 0; ie < 4; ie++) { pc[ie][0] = 0.f; pc[ie][1] = 0.f; pc[ie][2] = 0.f; }
            #pragma unroll
            for (int ie = 0; ie < 4; ie++)
                #pragma unroll
                for (int im = 0; im < 4; im++) {
                    float r = acc[ie][im];
                    pc[ie][0] += r * tmpreg[ie][im][0];
                    pc[ie][1] += r * tmpreg[ie][im][1];
                    pc[ie][2] += r * tmpreg[ie][im][2];
                }
            // reduce over the 8 m-groups (tx), all within one warp
            #pragma unroll
            for (int off = 1; off < 8; off <<= 1)
                #pragma unroll
                for (int ie = 0; ie < 4; ie++)
                    #pragma unroll
                    for (int d = 0; d < 3; d++)
                        pc[ie][d] += __shfl_xor_sync(0xffffffffu, pc[ie][d], off);
            if (tx == 0) {
                #pragma unroll
                for (int ie = 0; ie < 4; ie++)
                    #pragma unroll
                    for (int d = 0; d < 3; d++)
                        conv[(e0 + ie) * 72 + c * 3 + d] = pc[ie][d];
            }
        }
        __syncthreads();

        // ---- stage 5: attention scores, exp, denom atomics, stash v ----
        {
            int e = t >> 3, s = t & 7;   // 32 edges x 8 threads
            int ge = eg0 + e;
            if (ge < E) {
                if (s < 4) {   // s = head
                    float sc = 0.f;
                    #pragma unroll
                    for (int hd = 0; hd < 6; hd++)
                        sc += conv[e * 72 + s * 6 + hd] * conv[e * 72 + 24 + s * 6 + hd];
                    sc *= 0.20412414523193154f;           // 24^-0.5
                    sc = (sc >= 0.f) ? sc : 0.2f * sc;    // leaky_relu(0.2)
                    float ex = expf(sc);                  // shift-invariant softmax (scores ~O(1))
                    g_ex[ge * 4 + s] = ex;
                    atomicAdd(&g_denom[dsts[e] * 4 + s], ex);
                }
                #pragma unroll
                for (int jj = 0; jj < 3; jj++)
                    g_v[ge * 24 + s * 3 + jj] = conv[e * 72 + 48 + s * 3 + jj];
            }
        }
        __syncthreads();
    }
}

__global__ void initK(float* __restrict__ out, int N)
{
    int i = blockIdx.x * blockDim.x + threadIdx.x;
    if (i < N * 24) out[i] = 0.f;
    if (i < N * 4)  g_denom[i] = 0.f;
}

__global__ __launch_bounds__(256)
void passB(const int* __restrict__ dst, float* __restrict__ out, int E)
{
    int idx = blockIdx.x * blockDim.x + threadIdx.x;
    int e = idx >> 3, s = idx & 7;      // 8 threads/edge, 3 outputs each
    if (e >= E) return;
    int d = dst[e];
    int head = s >> 1;                   // j = s*3.. within a single head (6 % 3 == 0)
    float w = g_ex[e * 4 + head] / g_denom[d * 4 + head];
    #pragma unroll
    for (int jj = 0; jj < 3; jj++) {
        int j = s * 3 + jj;
        atomicAdd(&out[d * 24 + j], w * g_v[e * 24 + j]);
    }
}

extern "C" void kernel_launch(void* const* d_in, const int* in_sizes, int n_in,
                              void* d_out, int out_size)
{
    const int*   src   = (const int*)d_in[0];
    const int*   dst   = (const int*)d_in[1];
    const float* basis = (const float*)d_in[2];
    const float* efeat = (const float*)d_in[3];
    const float* f     = (const float*)d_in[4];
    const float* W1    = (const float*)d_in[5];
    const float* b1    = (const float*)d_in[6];
    const float* W2    = (const float*)d_in[7];
    const float* b2    = (const float*)d_in[8];
    float* out = (float*)d_out;

    int E = in_sizes[0];          // 160000
    int N = in_sizes[4] / 48;     // f is (N,16,3) -> 10000

    cudaFuncSetAttribute(passA, cudaFuncAttributeMaxDynamicSharedMemorySize, SMEM_BYTES);

    initK<<<(N * 24 + 255) / 256, 256>>>(out, N);

    int ntiles = (E + 31) / 32;
    int grid = ntiles < 148 ? ntiles : 148;
    passA<<<grid, 256, SMEM_BYTES>>>(src, dst, basis, efeat, f, W1, b1, W2, b2, E);

    passB<<<(E * 8 + 255) / 256, 256>>>(dst, out, E);
}

// round 4
// speedup vs baseline: 1.0027x; 1.0027x over previous
#include <cuda_runtime.h>

// Problem constants (fixed per metadata)
#define EMAX 160000
#define NMAX 10000

// Scratch (device globals — allocation-free)
__device__ float g_ex[EMAX * 4];      // exp(score) per edge/head
__device__ float g_v[EMAX * 24];      // v per edge (m2*d2 = 24)
__device__ float g_denom[NMAX * 4];   // softmax denominator per node/head

// Shared memory layout (in floats)
#define OFF_W2T 0        // [64][768]  W2 transposed (k-major)
#define OFF_W1T 49152    // [32][64]   W1 transposed (i-major)
#define OFF_HT  51200    // [64][32]   H (relu MLP out), k-major
#define OFF_BAS 53248    // [32][18]   basis per edge
#define OFF_FG  53824    // [32][48]   gathered f[src]
#define OFF_UNI 55360    // union: EF [32][33] (1056) / conv [32][72] (2304)
#define OFF_SRC 57664    // [32] int
#define OFF_DST 57696    // [32] int
#define SMEM_FLOATS 57728
#define SMEM_BYTES (SMEM_FLOATS * 4)   // 230912 B < 232448 B limit

__global__ __launch_bounds__(256, 1)
void passA(const int* __restrict__ src, const int* __restrict__ dst,
           const float* __restrict__ basis, const float* __restrict__ efeat,
           const float* __restrict__ f, const float* __restrict__ W1,
           const float* __restrict__ b1, const float* __restrict__ W2,
           const float* __restrict__ b2, int E)
{
    extern __shared__ float sm[];
    float* W2t = sm + OFF_W2T;
    float* W1t = sm + OFF_W1T;
    float* Ht  = sm + OFF_HT;
    float* bas = sm + OFF_BAS;
    float* fg  = sm + OFF_FG;
    float* uni = sm + OFF_UNI;
    int* srcs  = (int*)(sm + OFF_SRC);
    int* dsts  = (int*)(sm + OFF_DST);

    const int t = threadIdx.x;

    // ---- one-time per block: stage W2 (transposed, k-major) and W1 (transposed) ----
    for (int idx = t; idx < 768 * 64; idx += 256) {
        int o = idx >> 6, h = idx & 63;       // W2[o][h], o<768, h<64
        W2t[h * 768 + o] = W2[idx];
    }
    for (int idx = t; idx < 64 * 32; idx += 256) {
        int j = idx >> 5, i = idx & 31;       // W1[j][i], j<64, i<32
        W1t[i * 64 + j] = W1[idx];
    }
    __syncthreads();

    // GEMM thread mapping: 4 c-quadrants x (8 e-groups x 8 m-groups)
    const int cq = t >> 6;          // 0..3
    const int ty = (t >> 3) & 7;    // 0..7
    const int tx = t & 7;           // 0..7
    const int e0 = ty * 4;
    const int m0 = tx * 4;

    const int ntiles = (E + 31) >> 5;
    for (int tile = blockIdx.x; tile < ntiles; tile += gridDim.x) {
        const int eg0 = tile << 5;

        // ---- stage 1: edge indices ----
        if (t < 32) {
            int ee = min(eg0 + t, E - 1);
            srcs[t] = src[ee];
            dsts[t] = dst[ee];
        }
        __syncthreads();

        // ---- stage 2: edge feats (into union region), basis, gathered f ----
        for (int idx = t; idx < 1024; idx += 256) {      // EF [32][33] padded
            int e = idx >> 5, i = idx & 31;
            int ee = min(eg0 + e, E - 1);
            uni[e * 33 + i] = efeat[ee * 32 + i];
        }
        for (int idx = t; idx < 576; idx += 256) {       // basis [32][18]
            int e = idx / 18, k = idx - e * 18;
            int ee = min(eg0 + e, E - 1);
            bas[e * 18 + k] = basis[ee * 18 + k];
        }
        for (int idx = t; idx < 1536; idx += 256) {      // f gather [32][48]
            int e = idx / 48, r = idx - e * 48;
            fg[idx] = f[srcs[e] * 48 + r];
        }
        __syncthreads();

        // ---- stage 3a: tmp[e][m][d] into registers (48/thread) ----
        // m = m1*2 + rep ; tmp = sum_d1 f[src][m1][d1] * basis[d1][rep*3+d]
        float tmpreg[4][4][3];
        #pragma unroll
        for (int ie = 0; ie < 4; ie++) {
            int e = e0 + ie;
            #pragma unroll
            for (int im = 0; im < 4; im++) {
                int m = m0 + im;
                int m1 = m >> 1, rep = m & 1;
                #pragma unroll
                for (int d = 0; d < 3; d++) {
                    float s = 0.f;
                    #pragma unroll
                    for (int d1 = 0; d1 < 3; d1++)
                        s += fg[e * 48 + m1 * 3 + d1] * bas[e * 18 + d1 * 6 + rep * 3 + d];
                    tmpreg[ie][im][d] = s;
                }
            }
        }

        // ---- stage 3b: H = relu(EF @ W1^T + b1), stored k-major Ht[j][e] ----
        {
            int e = t & 31, jg = t >> 5;
            #pragma unroll
            for (int jj = 0; jj < 8; jj++) {
                int j = jg * 8 + jj;
                float acc = __ldg(&b1[j]);
                #pragma unroll
                for (int i = 0; i < 32; i++)
                    acc += uni[e * 33 + i] * W1t[i * 64 + j];   // EF lane-strided, W1t broadcast
                Ht[j * 32 + e] = fmaxf(acc, 0.f);
            }
        }
        __syncthreads();   // Ht ready; EF (union) now dead -> conv may overwrite

        // ---- stage 4: RW GEMM fused with conv contraction ----
        float* conv = uni;   // [32][72]: c*3+d flattened, k|q|v = c 0..7|8..15|16..23
        #pragma unroll 1
        for (int cg = 0; cg < 6; cg++) {
            const int c = cg * 4 + cq;
            float acc[4][4];
            {
                float bvals[4];
                #pragma unroll
                for (int im = 0; im < 4; im++)
                    bvals[im] = __ldg(&b2[c * 32 + m0 + im]);
                #pragma unroll
                for (int ie = 0; ie < 4; ie++)
                    #pragma unroll
                    for (int im = 0; im < 4; im++)
                        acc[ie][im] = bvals[im];
            }
            const float* Wp = W2t + c * 32 + m0;
            #pragma unroll 16
            for (int k = 0; k < 64; k++) {
                float4 av = *reinterpret_cast<const float4*>(Ht + k * 32 + e0);
                float4 bv = *reinterpret_cast<const float4*>(Wp + k * 768);
                acc[0][0] += av.x * bv.x; acc[0][1] += av.x * bv.y; acc[0][2] += av.x * bv.z; acc[0][3] += av.x * bv.w;
                acc[1][0] += av.y * bv.x; acc[1][1] += av.y * bv.y; acc[1][2] += av.y * bv.z; acc[1][3] += av.y * bv.w;
                acc[2][0] += av.z * bv.x; acc[2][1] += av.z * bv.y; acc[2][2] += av.z * bv.z; acc[2][3] += av.z * bv.w;
                acc[3][0] += av.w * bv.x; acc[3][1] += av.w * bv.y; acc[3][2] += av.w * bv.z; acc[3][3] += av.w * bv.w;
            }
            // local conv partial: pc[e][d] = sum_m rw[e][c][m] * tmp[e][m][d]
            float pc[4][3];
            #pragma unroll
            for (int ie = 0; ie < 4; ie++) { pc[ie][0] = 0.f; pc[ie][1] = 0.f; pc[ie][2] = 0.f; }
            #pragma unroll
            for (int ie = 0; ie < 4; ie++)
                #pragma unroll
                for (int im = 0; im < 4; im++) {
                    float r = acc[ie][im];
                    pc[ie][0] += r * tmpreg[ie][im][0];
                    pc[ie][1] += r * tmpreg[ie][im][1];
                    pc[ie][2] += r * tmpreg[ie][im][2];
                }
            // reduce over the 8 m-groups (tx), all within one warp
            #pragma unroll
            for (int off = 1; off < 8; off <<= 1)
                #pragma unroll
                for (int ie = 0; ie < 4; ie++)
                    #pragma unroll
                    for (int d = 0; d < 3; d++)
                        pc[ie][d] += __shfl_xor_sync(0xffffffffu, pc[ie][d], off);
            if (tx == 0) {
                #pragma unroll
                for (int ie = 0; ie < 4; ie++)
                    #pragma unroll
                    for (int d = 0; d < 3; d++)
                        conv[(e0 + ie) * 72 + c * 3 + d] = pc[ie][d];
            }
        }
        __syncthreads();

        // ---- stage 5: attention scores, exp, denom atomics, stash v ----
        {
            int e = t >> 3, s = t & 7;   // 32 edges x 8 threads
            int ge = eg0 + e;
            if (ge < E) {
                if (s < 4) {   // s = head
                    float sc = 0.f;
                    #pragma unroll
                    for (int hd = 0; hd < 6; hd++)
                        sc += conv[e * 72 + s * 6 + hd] * conv[e * 72 + 24 + s * 6 + hd];
                    sc *= 0.20412414523193154f;           // 24^-0.5
                    sc = (sc >= 0.f) ? sc : 0.2f * sc;    // leaky_relu(0.2)
                    float ex = expf(sc);                  // shift-invariant softmax (scores ~O(1))
                    g_ex[ge * 4 + s] = ex;
                    atomicAdd(&g_denom[dsts[e] * 4 + s], ex);
                }
                #pragma unroll
                for (int jj = 0; jj < 3; jj++)
                    g_v[ge * 24 + s * 3 + jj] = conv[e * 72 + 48 + s * 3 + jj];
            }
        }
        __syncthreads();
    }
}

__global__ void initK(float* __restrict__ out, int N)
{
    int i = blockIdx.x * blockDim.x + threadIdx.x;
    if (i < N * 24) out[i] = 0.f;
    if (i < N * 4)  g_denom[i] = 0.f;
}

__global__ __launch_bounds__(256)
void passB(const int* __restrict__ dst, float* __restrict__ out, int E)
{
    int idx = blockIdx.x * blockDim.x + threadIdx.x;
    int e = idx >> 3, s = idx & 7;      // 8 threads/edge, 3 outputs each
    if (e >= E) return;
    int d = dst[e];
    int head = s >> 1;                   // j = s*3.. within a single head (6 % 3 == 0)
    float w = g_ex[e * 4 + head] / g_denom[d * 4 + head];
    #pragma unroll
    for (int jj = 0; jj < 3; jj++) {
        int j = s * 3 + jj;
        atomicAdd(&out[d * 24 + j], w * g_v[e * 24 + j]);
    }
}

extern "C" void kernel_launch(void* const* d_in, const int* in_sizes, int n_in,
                              void* d_out, int out_size)
{
    const int*   src   = (const int*)d_in[0];
    const int*   dst   = (const int*)d_in[1];
    const float* basis = (const float*)d_in[2];
    const float* efeat = (const float*)d_in[3];
    const float* f     = (const float*)d_in[4];
    const float* W1    = (const float*)d_in[5];
    const float* b1    = (const float*)d_in[6];
    const float* W2    = (const float*)d_in[7];
    const float* b2    = (const float*)d_in[8];
    float* out = (float*)d_out;

    int E = in_sizes[0];          // 160000
    int N = in_sizes[4] / 48;     // f is (N,16,3) -> 10000

    cudaFuncSetAttribute(passA, cudaFuncAttributeMaxDynamicSharedMemorySize, SMEM_BYTES);

    initK<<<(N * 24 + 255) / 256, 256>>>(out, N);

    int ntiles = (E + 31) / 32;
    int grid = ntiles < 148 ? ntiles : 148;
    passA<<<grid, 256, SMEM_BYTES>>>(src, dst, basis, efeat, f, W1, b1, W2, b2, E);

    passB<<<(E * 8 + 255) / 256, 256>>>(dst, out, E);
}

// round 5
// speedup vs baseline: 1.1056x; 1.1027x over previous
#include <cuda_runtime.h>

// Problem constants (fixed per metadata)
#define EMAX 160000
#define NMAX 10000

// Scratch (device globals — allocation-free)
__device__ float g_ex[EMAX * 4];      // exp(score) per edge/head
__device__ float g_v[EMAX * 24];      // v per edge (m2*d2 = 24)
__device__ float g_denom[NMAX * 4];   // softmax denominator per node/head

// Packed fp32x2 FMA (Blackwell): d.lo += a.lo*b.lo ; d.hi += a.hi*b.hi
#define FMA_F32X2(d, a, b) \
    asm("fma.rn.f32x2 %0, %1, %2, %0;" : "+l"(d) : "l"(a), "l"(b))

// Shared memory layout (in floats)
#define OFF_W2S 0        // [768][64]  W2 original layout, quad-XOR swizzled rows
#define OFF_W1S 49152    // [64][32]   W1 original layout (k contiguous)
#define OFF_H   51200    // [32][64]   H e-major, quad-XOR swizzled rows
#define OFF_BAS 53248    // [32][18]   basis per edge
#define OFF_FG  53824    // [32][48]   gathered f[src]
#define OFF_UNI 55360    // union: EF [32][34] (1088) / conv [32][72] (2304)
#define OFF_SRC 57664    // [32] int
#define OFF_DST 57696    // [32] int
#define SMEM_FLOATS 57728
#define SMEM_BYTES (SMEM_FLOATS * 4)   // 230912 B

__global__ __launch_bounds__(256, 1)
void passA(const int* __restrict__ src, const int* __restrict__ dst,
           const float* __restrict__ basis, const float* __restrict__ efeat,
           const float* __restrict__ f, const float* __restrict__ W1,
           const float* __restrict__ b1, const float* __restrict__ W2,
           const float* __restrict__ b2, int E)
{
    extern __shared__ float sm[];
    float* W2s = sm + OFF_W2S;
    float* W1s = sm + OFF_W1S;
    float* Hs  = sm + OFF_H;
    float* bas = sm + OFF_BAS;
    float* fg  = sm + OFF_FG;
    float* uni = sm + OFF_UNI;
    int* srcs  = (int*)(sm + OFF_SRC);
    int* dsts  = (int*)(sm + OFF_DST);

    const int t = threadIdx.x;

    // ---- one-time per block: stage W2 (quad-swizzled, k-contiguous) and W1 ----
    for (int idx = t; idx < 768 * 64; idx += 256) {
        int o = idx >> 6, k = idx & 63;
        int q = k >> 2, key = (o >> 2) & 7;
        W2s[(o << 6) | ((q ^ key) << 2) | (k & 3)] = W2[idx];
    }
    for (int idx = t; idx < 64 * 32; idx += 256)
        W1s[idx] = W1[idx];
    __syncthreads();

    // GEMM thread mapping: 4 c-quadrants x (8 e-groups x 8 m-groups)
    const int cq = t >> 6;          // 0..3
    const int ty = (t >> 3) & 7;    // 0..7  (4 consecutive values per warp)
    const int tx = t & 7;           // 0..7
    const int e0 = ty * 4;
    const int m0 = tx * 4;
    const int keyA = ty & 7;        // (e>>2)&7, same for all 4 edges of this thread
    const int keyB = tx & 7;        // (m>>2)&7, same for all 4 m of this thread

    const int ntiles = (E + 31) >> 5;
    for (int tile = blockIdx.x; tile < ntiles; tile += gridDim.x) {
        const int eg0 = tile << 5;

        // ---- stage 1: edge indices ----
        if (t < 32) {
            int ee = min(eg0 + t, E - 1);
            srcs[t] = src[ee];
            dsts[t] = dst[ee];
        }
        __syncthreads();

        // ---- stage 2: edge feats (union region, [32][34] pad), basis, gathered f ----
        for (int idx = t; idx < 1024; idx += 256) {
            int e = idx >> 5, i = idx & 31;
            int ee = min(eg0 + e, E - 1);
            uni[e * 34 + i] = efeat[ee * 32 + i];
        }
        for (int idx = t; idx < 576; idx += 256) {       // basis [32][18]
            int e = idx / 18, k = idx - e * 18;
            int ee = min(eg0 + e, E - 1);
            bas[e * 18 + k] = basis[ee * 18 + k];
        }
        for (int idx = t; idx < 1536; idx += 256) {      // f gather [32][48]
            int e = idx / 48, r = idx - e * 48;
            fg[idx] = f[srcs[e] * 48 + r];
        }
        __syncthreads();

        // ---- stage 3a: tmp[e][m][d] into registers (48/thread) ----
        float tmpreg[4][4][3];
        #pragma unroll
        for (int ie = 0; ie < 4; ie++) {
            int e = e0 + ie;
            #pragma unroll
            for (int im = 0; im < 4; im++) {
                int m = m0 + im;
                int m1 = m >> 1, rep = m & 1;
                #pragma unroll
                for (int d = 0; d < 3; d++) {
                    float s = 0.f;
                    #pragma unroll
                    for (int d1 = 0; d1 < 3; d1++)
                        s += fg[e * 48 + m1 * 3 + d1] * bas[e * 18 + d1 * 6 + rep * 3 + d];
                    tmpreg[ie][im][d] = s;
                }
            }
        }

        // ---- stage 3b: H = relu(EF @ W1^T + b1), packed f32x2 over k-pairs ----
        {
            int e = t & 31;           // = lane id
            int jg = t >> 5;          // = warp id, constant per warp (W1 row broadcasts)
            unsigned long long ef[16];
            #pragma unroll
            for (int p = 0; p < 16; p++)
                ef[p] = *reinterpret_cast<const unsigned long long*>(uni + e * 34 + p * 2);
            int ekey = (e >> 2) & 7;
            #pragma unroll
            for (int jj = 0; jj < 8; jj++) {
                int j = jg * 8 + jj;
                const float* wrow = W1s + j * 32;
                unsigned long long acc = 0ull;
                #pragma unroll
                for (int p = 0; p < 16; p++) {
                    unsigned long long w =
                        *reinterpret_cast<const unsigned long long*>(wrow + p * 2);
                    FMA_F32X2(acc, ef[p], w);
                }
                float lo = __uint_as_float((unsigned)acc);
                float hi = __uint_as_float((unsigned)(acc >> 32));
                float a = lo + hi + __ldg(&b1[j]);
                Hs[(e << 6) | ((((j >> 2) ^ ekey) << 2) | (j & 3))] = fmaxf(a, 0.f);
            }
        }
        __syncthreads();   // Hs ready; EF (union) now dead -> conv may overwrite

        // ---- stage 4: RW GEMM (f32x2 packed, k-pair accumulators) + conv fuse ----
        float* conv = uni;   // [32][72]
        #pragma unroll 1
        for (int cg = 0; cg < 6; cg++) {
            const int c = cg * 4 + cq;
            unsigned long long acc2[4][4];
            #pragma unroll
            for (int ie = 0; ie < 4; ie++)
                #pragma unroll
                for (int im = 0; im < 4; im++)
                    acc2[ie][im] = 0ull;

            const float* Wb = W2s + (c * 32 + m0) * 64;
            #pragma unroll
            for (int q = 0; q < 16; q++) {
                const int qa = (q ^ keyA) << 2;
                const int qb = (q ^ keyB) << 2;
                ulonglong2 a[4], b[4];
                #pragma unroll
                for (int ie = 0; ie < 4; ie++)
                    a[ie] = *reinterpret_cast<const ulonglong2*>(Hs + ((e0 + ie) << 6) + qa);
                #pragma unroll
                for (int im = 0; im < 4; im++)
                    b[im] = *reinterpret_cast<const ulonglong2*>(Wb + (im << 6) + qb);
                #pragma unroll
                for (int ie = 0; ie < 4; ie++)
                    #pragma unroll
                    for (int im = 0; im < 4; im++) {
                        FMA_F32X2(acc2[ie][im], a[ie].x, b[im].x);
                        FMA_F32X2(acc2[ie][im], a[ie].y, b[im].y);
                    }
            }

            // epilogue: rw = lo+hi+bias; fuse conv partial
            float bvals[4];
            #pragma unroll
            for (int im = 0; im < 4; im++)
                bvals[im] = __ldg(&b2[c * 32 + m0 + im]);

            float pc[4][3];
            #pragma unroll
            for (int ie = 0; ie < 4; ie++) { pc[ie][0] = 0.f; pc[ie][1] = 0.f; pc[ie][2] = 0.f; }
            #pragma unroll
            for (int ie = 0; ie < 4; ie++)
                #pragma unroll
                for (int im = 0; im < 4; im++) {
                    unsigned long long v = acc2[ie][im];
                    float r = __uint_as_float((unsigned)v)
                            + __uint_as_float((unsigned)(v >> 32)) + bvals[im];
                    pc[ie][0] += r * tmpreg[ie][im][0];
                    pc[ie][1] += r * tmpreg[ie][im][1];
                    pc[ie][2] += r * tmpreg[ie][im][2];
                }
            // reduce over the 8 m-groups (tx) within one warp
            #pragma unroll
            for (int off = 1; off < 8; off <<= 1)
                #pragma unroll
                for (int ie = 0; ie < 4; ie++)
                    #pragma unroll
                    for (int d = 0; d < 3; d++)
                        pc[ie][d] += __shfl_xor_sync(0xffffffffu, pc[ie][d], off);
            if (tx == 0) {
                #pragma unroll
                for (int ie = 0; ie < 4; ie++)
                    #pragma unroll
                    for (int d = 0; d < 3; d++)
                        conv[(e0 + ie) * 72 + c * 3 + d] = pc[ie][d];
            }
        }
        __syncthreads();

        // ---- stage 5: attention scores, exp, denom atomics, stash v ----
        {
            int e = t >> 3, s = t & 7;   // 32 edges x 8 threads
            int ge = eg0 + e;
            if (ge < E) {
                if (s < 4) {   // s = head
                    float sc = 0.f;
                    #pragma unroll
                    for (int hd = 0; hd < 6; hd++)
                        sc += conv[e * 72 + s * 6 + hd] * conv[e * 72 + 24 + s * 6 + hd];
                    sc *= 0.20412414523193154f;           // 24^-0.5
                    sc = (sc >= 0.f) ? sc : 0.2f * sc;    // leaky_relu(0.2)
                    float ex = expf(sc);                  // shift-invariant softmax (scores ~O(1))
                    g_ex[ge * 4 + s] = ex;
                    atomicAdd(&g_denom[dsts[e] * 4 + s], ex);
                }
                #pragma unroll
                for (int jj = 0; jj < 3; jj++)
                    g_v[ge * 24 + s * 3 + jj] = conv[e * 72 + 48 + s * 3 + jj];
            }
        }
        __syncthreads();
    }
}

__global__ void initK(float* __restrict__ out, int N)
{
    int i = blockIdx.x * blockDim.x + threadIdx.x;
    if (i < N * 24) out[i] = 0.f;
    if (i < N * 4)  g_denom[i] = 0.f;
}

__global__ __launch_bounds__(256)
void passB(const int* __restrict__ dst, float* __restrict__ out, int E)
{
    int idx = blockIdx.x * blockDim.x + threadIdx.x;
    int e = idx >> 3, s = idx & 7;      // 8 threads/edge, 3 outputs each
    if (e >= E) return;
    int d = dst[e];
    int head = s >> 1;                   // 6 floats/head, 3 per thread
    float w = g_ex[e * 4 + head] / g_denom[d * 4 + head];
    #pragma unroll
    for (int jj = 0; jj < 3; jj++) {
        int j = s * 3 + jj;
        atomicAdd(&out[d * 24 + j], w * g_v[e * 24 + j]);
    }
}

extern "C" void kernel_launch(void* const* d_in, const int* in_sizes, int n_in,
                              void* d_out, int out_size)
{
    const int*   src   = (const int*)d_in[0];
    const int*   dst   = (const int*)d_in[1];
    const float* basis = (const float*)d_in[2];
    const float* efeat = (const float*)d_in[3];
    const float* f     = (const float*)d_in[4];
    const float* W1    = (const float*)d_in[5];
    const float* b1    = (const float*)d_in[6];
    const float* W2    = (const float*)d_in[7];
    const float* b2    = (const float*)d_in[8];
    float* out = (float*)d_out;

    int E = in_sizes[0];          // 160000
    int N = in_sizes[4] / 48;     // f is (N,16,3) -> 10000

    cudaFuncSetAttribute(passA, cudaFuncAttributeMaxDynamicSharedMemorySize, SMEM_BYTES);

    initK<<<(N * 24 + 255) / 256, 256>>>(out, N);

    int ntiles = (E + 31) / 32;
    int grid = ntiles < 148 ? ntiles : 148;
    passA<<<grid, 256, SMEM_BYTES>>>(src, dst, basis, efeat, f, W1, b1, W2, b2, E);

    passB<<<(E * 8 + 255) / 256, 256>>>(dst, out, E);
}